// round 5
// baseline (speedup 1.0000x reference)
#include <cuda_runtime.h>
#include <cuda_bf16.h>
#include <mma.h>
#include <cstdint>
#include <math.h>

using namespace nvcuda;

#define N_NODES 100000
#define N_EDGES 600000
#define D 128
#define NGRAPH 64
#define NUM_LAYER 3

// ---------------- scratch (static device globals; no allocation) ----------------
__device__ float g_bufA[(size_t)N_NODES * D];
__device__ float g_bufB[(size_t)N_NODES * D];
__device__ int   g_gstart[NGRAPH + 1];
// CSR scratch (2 relations)
__device__ int g_rowptr[2][N_NODES + 1];
__device__ int g_cursor[2][N_NODES];
__device__ int g_csrsrc[2][N_EDGES];
__device__ int g_bsums[2][512];
// pre-split weight planes: per (layer,rel): [W1h, W1l, W2h, W2l]
__device__ __nv_bfloat16 g_wplanes[(size_t)NUM_LAYER * 2 * 4 * D * D];

// split fp32 pair into bf16 hi plane + bf16 residual plane (packed bf16x2)
__device__ __forceinline__ void split2(float a, float b, uint32_t& hi, uint32_t& lo) {
    __nv_bfloat16 ha = __float2bfloat16(a), hb = __float2bfloat16(b);
    float ra = a - __bfloat162float(ha);
    float rb = b - __bfloat162float(hb);
    __nv_bfloat162 H; H.x = ha; H.y = hb;
    __nv_bfloat162 L; L.x = __float2bfloat16(ra); L.y = __float2bfloat16(rb);
    hi = *(uint32_t*)&H;
    lo = *(uint32_t*)&L;
}

// ---------------- weight pre-split (runs once per call) --------------------------
__global__ void wsplit_kernel(const float* __restrict__ l1w,
                              const float* __restrict__ l2w,
                              __nv_bfloat16* __restrict__ wp) {
    int i = blockIdx.x * blockDim.x + threadIdx.x;   // over 6 mats * 8192 pairs
    if (i >= NUM_LAYER * 2 * (D * D / 2)) return;
    int mat = i / (D * D / 2);
    int p = i % (D * D / 2);
    float2 a = ((const float2*)l1w)[i];
    float2 b = ((const float2*)l2w)[i];
    uint32_t h, l;
    size_t base = (size_t)mat * 4 * D * D;
    split2(a.x, a.y, h, l);
    ((uint32_t*)&wp[base + 0 * D * D])[p] = h;
    ((uint32_t*)&wp[base + 1 * D * D])[p] = l;
    split2(b.x, b.y, h, l);
    ((uint32_t*)&wp[base + 2 * D * D])[p] = h;
    ((uint32_t*)&wp[base + 3 * D * D])[p] = l;
}

// ---------------- smem layout (bytes) -------------------------------------------
#define SSTRIDE 144                      // elements; 288 B rows
#define PLANE_BYTES (128 * SSTRIDE * 2)  // 36864
#define SM_B1      0
#define SM_B2      512
#define SM_SCRATCH 1024                  // 8 warps x 256 floats = 8192 B
#define SM_AH      (SM_SCRATCH + 8192)
#define SM_AL      (SM_AH + PLANE_BYTES)
#define SM_W1H     (SM_AL + PLANE_BYTES)
#define SM_W1L     (SM_W1H + PLANE_BYTES)
#define SM_W2H     (SM_W1L + PLANE_BYTES)
#define SM_W2L     (SM_W2H + PLANE_BYTES)
#define SM_TOTAL   (SM_W2L + PLANE_BYTES)   // 230400 bytes

typedef wmma::fragment<wmma::matrix_a, 16, 16, 16, __nv_bfloat16, wmma::row_major> AFrag;
typedef wmma::fragment<wmma::matrix_b, 16, 16, 16, __nv_bfloat16, wmma::row_major> BFrag;
typedef wmma::fragment<wmma::accumulator, 16, 16, 16, float> CFrag;

// ======= fused gather + GIN MLP: out (+)= f( relu((h+Σh_nbr)@W1+b1)@W2 + b2 ) ====
__global__ void __launch_bounds__(256, 1)
gin_fused_kernel(const float* __restrict__ h,
                 const int* __restrict__ rowptr,
                 const int* __restrict__ csrsrc,
                 const __nv_bfloat16* __restrict__ wp,   // 4 planes for this (l,rel)
                 const float* __restrict__ b1, const float* __restrict__ b2,
                 float* __restrict__ out, int accumulate, int relu_out) {
    extern __shared__ char sm[];
    float* b1s = (float*)(sm + SM_B1);
    float* b2s = (float*)(sm + SM_B2);
    __nv_bfloat16* sAh  = (__nv_bfloat16*)(sm + SM_AH);
    __nv_bfloat16* sAl  = (__nv_bfloat16*)(sm + SM_AL);
    __nv_bfloat16* sW1h = (__nv_bfloat16*)(sm + SM_W1H);
    __nv_bfloat16* sW1l = (__nv_bfloat16*)(sm + SM_W1L);
    __nv_bfloat16* sW2h = (__nv_bfloat16*)(sm + SM_W2H);
    __nv_bfloat16* sW2l = (__nv_bfloat16*)(sm + SM_W2L);

    const int tid = threadIdx.x;
    const int wid = tid >> 5;
    const int lane = tid & 31;
    const int row0 = blockIdx.x * 128;

    if (tid < 128) { b1s[tid] = b1[tid]; b2s[tid] = b2[tid]; }

    // ---- weight planes: pure bf16 copies (pre-split in gmem) ----
    {
        const uint4* w1hv = (const uint4*)(wp + 0 * D * D);
        const uint4* w1lv = (const uint4*)(wp + 1 * D * D);
        const uint4* w2hv = (const uint4*)(wp + 2 * D * D);
        const uint4* w2lv = (const uint4*)(wp + 3 * D * D);
        for (int i = tid; i < 128 * 16; i += 256) {
            int k = i >> 4, c = i & 15;       // c*8 bf16 offset
            *(uint4*)&sW1h[k * SSTRIDE + c * 8] = w1hv[i];
            *(uint4*)&sW1l[k * SSTRIDE + c * 8] = w1lv[i];
            *(uint4*)&sW2h[k * SSTRIDE + c * 8] = w2hv[i];
            *(uint4*)&sW2l[k * SSTRIDE + c * 8] = w2lv[i];
        }
    }

    // ---- A tile: fused CSR gather (h[row] + sum of neighbors), split to bf16 ----
    for (int j = 0; j < 16; j++) {
        int m = wid * 16 + j;
        int row = row0 + m;
        float4 acc = make_float4(0.f, 0.f, 0.f, 0.f);
        if (row < N_NODES) {
            acc = ((const float4*)(h + (size_t)row * D))[lane];
            int s = __ldg(&rowptr[row]), e = __ldg(&rowptr[row + 1]);
            for (int i = s; i < e; i++) {
                int src = __ldg(&csrsrc[i]);
                float4 v = ((const float4*)(h + (size_t)src * D))[lane];
                acc.x += v.x; acc.y += v.y; acc.z += v.z; acc.w += v.w;
            }
        }
        uint32_t hi, lo;
        split2(acc.x, acc.y, hi, lo);
        *(uint32_t*)&sAh[m * SSTRIDE + 4 * lane] = hi;
        *(uint32_t*)&sAl[m * SSTRIDE + 4 * lane] = lo;
        split2(acc.z, acc.w, hi, lo);
        *(uint32_t*)&sAh[m * SSTRIDE + 4 * lane + 2] = hi;
        *(uint32_t*)&sAl[m * SSTRIDE + 4 * lane + 2] = lo;
    }
    __syncthreads();

    // warp tiling: 4 warps in M (32 rows each), 2 warps in N (64 cols each)
    const int mwarp = wid >> 1;
    const int nwarp = wid & 1;
    const int m0 = mwarp * 32;
    const int n0w = nwarp * 64;
    float* sw = (float*)(sm + SM_SCRATCH) + wid * 256;   // 16x16 fp32 per warp
    const int r = lane >> 1, half = lane & 1;

    CFrag acc[2][4];

    // =================== GEMM1: D1 = A @ W1 (3 split terms) ===================
#pragma unroll
    for (int mt = 0; mt < 2; mt++)
#pragma unroll
        for (int nt = 0; nt < 4; nt++) wmma::fill_fragment(acc[mt][nt], 0.f);

    for (int k = 0; k < 128; k += 16) {
        AFrag ah[2], al[2];
#pragma unroll
        for (int mt = 0; mt < 2; mt++) {
            wmma::load_matrix_sync(ah[mt], sAh + (m0 + mt * 16) * SSTRIDE + k, SSTRIDE);
            wmma::load_matrix_sync(al[mt], sAl + (m0 + mt * 16) * SSTRIDE + k, SSTRIDE);
        }
#pragma unroll
        for (int nt = 0; nt < 4; nt++) {
            BFrag bh, bl;
            wmma::load_matrix_sync(bh, sW1h + k * SSTRIDE + n0w + nt * 16, SSTRIDE);
            wmma::load_matrix_sync(bl, sW1l + k * SSTRIDE + n0w + nt * 16, SSTRIDE);
#pragma unroll
            for (int mt = 0; mt < 2; mt++) {
                wmma::mma_sync(acc[mt][nt], ah[mt], bh, acc[mt][nt]);
                wmma::mma_sync(acc[mt][nt], ah[mt], bl, acc[mt][nt]);
                wmma::mma_sync(acc[mt][nt], al[mt], bh, acc[mt][nt]);
            }
        }
    }
    __syncthreads();   // all warps done reading A planes before overwrite

    // ---- epilogue1: z = relu(D1 + b1) -> re-split into A planes ----
#pragma unroll
    for (int mt = 0; mt < 2; mt++) {
#pragma unroll
        for (int nt = 0; nt < 4; nt++) {
            wmma::store_matrix_sync(sw, acc[mt][nt], 16, wmma::mem_row_major);
            __syncwarp();
#pragma unroll
            for (int q = 0; q < 4; q++) {
                int c0 = half * 8 + 2 * q;
                int n0 = n0w + nt * 16 + c0;
                float z0 = fmaxf(sw[r * 16 + c0]     + b1s[n0],     0.f);
                float z1 = fmaxf(sw[r * 16 + c0 + 1] + b1s[n0 + 1], 0.f);
                uint32_t hi, lo;
                split2(z0, z1, hi, lo);
                int mrow = m0 + mt * 16 + r;
                *(uint32_t*)&sAh[mrow * SSTRIDE + n0] = hi;
                *(uint32_t*)&sAl[mrow * SSTRIDE + n0] = lo;
            }
            __syncwarp();
        }
    }
    __syncthreads();   // full Z tile visible to all warps

    // =================== GEMM2: D2 = Z @ W2 (3 split terms) ===================
#pragma unroll
    for (int mt = 0; mt < 2; mt++)
#pragma unroll
        for (int nt = 0; nt < 4; nt++) wmma::fill_fragment(acc[mt][nt], 0.f);

    for (int k = 0; k < 128; k += 16) {
        AFrag ah[2], al[2];
#pragma unroll
        for (int mt = 0; mt < 2; mt++) {
            wmma::load_matrix_sync(ah[mt], sAh + (m0 + mt * 16) * SSTRIDE + k, SSTRIDE);
            wmma::load_matrix_sync(al[mt], sAl + (m0 + mt * 16) * SSTRIDE + k, SSTRIDE);
        }
#pragma unroll
        for (int nt = 0; nt < 4; nt++) {
            BFrag bh, bl;
            wmma::load_matrix_sync(bh, sW2h + k * SSTRIDE + n0w + nt * 16, SSTRIDE);
            wmma::load_matrix_sync(bl, sW2l + k * SSTRIDE + n0w + nt * 16, SSTRIDE);
#pragma unroll
            for (int mt = 0; mt < 2; mt++) {
                wmma::mma_sync(acc[mt][nt], ah[mt], bh, acc[mt][nt]);
                wmma::mma_sync(acc[mt][nt], ah[mt], bl, acc[mt][nt]);
                wmma::mma_sync(acc[mt][nt], al[mt], bh, acc[mt][nt]);
            }
        }
    }

    // ---- epilogue2: out (+)= maybe_relu(D2 + b2) ----
#pragma unroll
    for (int mt = 0; mt < 2; mt++) {
        const int row = row0 + m0 + mt * 16 + r;
#pragma unroll
        for (int nt = 0; nt < 4; nt++) {
            wmma::store_matrix_sync(sw, acc[mt][nt], 16, wmma::mem_row_major);
            __syncwarp();
            if (row < N_NODES) {
                int n0 = n0w + nt * 16 + half * 8;
                float* op = out + (size_t)row * D + n0;
                float v[8];
#pragma unroll
                for (int j = 0; j < 8; j++) v[j] = sw[r * 16 + half * 8 + j] + b2s[n0 + j];
                if (accumulate) {
                    float4 o0 = *(const float4*)(op);
                    float4 o1 = *(const float4*)(op + 4);
                    v[0] += o0.x; v[1] += o0.y; v[2] += o0.z; v[3] += o0.w;
                    v[4] += o1.x; v[5] += o1.y; v[6] += o1.z; v[7] += o1.w;
                }
                if (relu_out) {
#pragma unroll
                    for (int j = 0; j < 8; j++) v[j] = fmaxf(v[j], 0.f);
                }
                *(float4*)(op)     = make_float4(v[0], v[1], v[2], v[3]);
                *(float4*)(op + 4) = make_float4(v[4], v[5], v[6], v[7]);
            }
            __syncwarp();
        }
    }
}

// ---------------- node input embedding ------------------------------------------
__global__ void embed_kernel(const int* __restrict__ x,
                             const float* __restrict__ type_emb,
                             const float* __restrict__ output_emb,
                             float* __restrict__ h) {
    int tid = blockIdx.x * blockDim.x + threadIdx.x;
    int node = tid >> 5;
    int c = tid & 31;
    if (node >= N_NODES) return;
    int t = x[node * 2 + 0];
    int o = x[node * 2 + 1];
    float4 a = ((const float4*)(type_emb + (size_t)t * D))[c];
    float4 b = ((const float4*)(output_emb + (size_t)o * D))[c];
    ((float4*)(h + (size_t)node * D))[c] =
        make_float4(a.x + b.x, a.y + b.y, a.z + b.z, a.w + b.w);
}

// ---------------- CSR build -------------------------------------------------------
__global__ void hist_kernel(const int* __restrict__ ei, int* __restrict__ rowptr) {
    int e = blockIdx.x * blockDim.x + threadIdx.x;
    if (e >= N_EDGES) return;
    atomicAdd(&rowptr[ei[N_EDGES + e] + 1], 1);
}
__global__ void scan1_kernel(int* __restrict__ rowptr, int* __restrict__ bsums) {
    __shared__ int s[256];
    int idx = blockIdx.x * 256 + threadIdx.x;
    int v = (idx < N_NODES) ? rowptr[idx + 1] : 0;
    s[threadIdx.x] = v;
    __syncthreads();
#pragma unroll
    for (int o = 1; o < 256; o <<= 1) {
        int t = (threadIdx.x >= o) ? s[threadIdx.x - o] : 0;
        __syncthreads();
        s[threadIdx.x] += t;
        __syncthreads();
    }
    if (idx < N_NODES) rowptr[idx + 1] = s[threadIdx.x];
    if (threadIdx.x == 255) bsums[blockIdx.x] = s[255];
}
__global__ void scan2_kernel(int* __restrict__ bsums, int nb) {
    __shared__ int s[512];
    int t = threadIdx.x;
    int v = (t < nb) ? bsums[t] : 0;
    s[t] = v;
    __syncthreads();
#pragma unroll
    for (int o = 1; o < 512; o <<= 1) {
        int x = (t >= o) ? s[t - o] : 0;
        __syncthreads();
        s[t] += x;
        __syncthreads();
    }
    if (t < nb) bsums[t] = s[t] - v;   // exclusive prefix
}
__global__ void scan3_kernel(int* __restrict__ rowptr, const int* __restrict__ bsums) {
    int idx = blockIdx.x * 256 + threadIdx.x;
    if (idx < N_NODES) rowptr[idx + 1] += bsums[blockIdx.x];
}
__global__ void fill_kernel(const int* __restrict__ ei, int* __restrict__ cursor,
                            int* __restrict__ csrsrc) {
    int e = blockIdx.x * blockDim.x + threadIdx.x;
    if (e >= N_EDGES) return;
    int src = ei[e];
    int dst = ei[N_EDGES + e];
    int pos = atomicAdd(&cursor[dst], 1);
    csrsrc[pos] = src;
}

// ---------------- graph segment boundaries ---------------------------------------
__global__ void bounds_kernel(const int* __restrict__ batch) {
    int g = threadIdx.x;
    if (g > NGRAPH) return;
    int lo = 0, hi = N_NODES;
    while (lo < hi) {
        int mid = (lo + hi) >> 1;
        if (batch[mid] < g) lo = mid + 1; else hi = mid;
    }
    g_gstart[g] = lo;
}

// ---------------- pooling --------------------------------------------------------
__global__ void pool_kernel(const float* __restrict__ h, float* __restrict__ out,
                            int out_size) {
    int b = blockIdx.x;
    int c = threadIdx.x;
    int s = g_gstart[b], e = g_gstart[b + 1];
    float s0 = 0.f, s1 = 0.f, s2 = 0.f, s3 = 0.f;
    float mx = -INFINITY, mn = INFINITY;
    int r = s;
    for (; r + 4 <= e; r += 4) {
        float v0 = h[(size_t)(r + 0) * D + c];
        float v1 = h[(size_t)(r + 1) * D + c];
        float v2 = h[(size_t)(r + 2) * D + c];
        float v3 = h[(size_t)(r + 3) * D + c];
        s0 += v0; s1 += v1; s2 += v2; s3 += v3;
        mx = fmaxf(mx, fmaxf(fmaxf(v0, v1), fmaxf(v2, v3)));
        mn = fminf(mn, fminf(fminf(v0, v1), fminf(v2, v3)));
    }
    for (; r < e; r++) {
        float v = h[(size_t)r * D + c];
        s0 += v; mx = fmaxf(mx, v); mn = fminf(mn, v);
    }
    float sum = (s0 + s1) + (s2 + s3);
    float cnt = (float)(e - s);
    float mean = sum / fmaxf(cnt, 1.f);
    float vals[4] = { sum, mean, mx, mn };
#pragma unroll
    for (int a = 0; a < 4; a++) {
        int m = a * D + c;
        out[b * 512 + (m & 3) * 128 + (m >> 2)] = vals[a];
    }
    if (c < 4) {
        int idx = NGRAPH * 4 * D + b * 4 + c;
        if (idx < out_size) out[idx] = 1.0f;
    }
}

// ---------------- launch ---------------------------------------------------------
extern "C" void kernel_launch(void* const* d_in, const int* in_sizes, int n_in,
                              void* d_out, int out_size) {
    const int*   x          = (const int*)d_in[0];
    const int*   e_pos      = (const int*)d_in[1];
    const int*   e_inv      = (const int*)d_in[2];
    const int*   batch      = (const int*)d_in[3];
    const float* type_emb   = (const float*)d_in[4];
    const float* output_emb = (const float*)d_in[5];
    const float* l1w        = (const float*)d_in[6];
    const float* l1b        = (const float*)d_in[7];
    const float* l2w        = (const float*)d_in[8];
    const float* l2b        = (const float*)d_in[9];
    float* out = (float*)d_out;

    float *hA, *hB;
    int *rowptr, *cursor, *csrsrc, *bsums;
    __nv_bfloat16* wp;
    cudaGetSymbolAddress((void**)&hA, g_bufA);
    cudaGetSymbolAddress((void**)&hB, g_bufB);
    cudaGetSymbolAddress((void**)&rowptr, g_rowptr);
    cudaGetSymbolAddress((void**)&cursor, g_cursor);
    cudaGetSymbolAddress((void**)&csrsrc, g_csrsrc);
    cudaGetSymbolAddress((void**)&bsums, g_bsums);
    cudaGetSymbolAddress((void**)&wp, g_wplanes);

    cudaFuncSetAttribute(gin_fused_kernel,
                         cudaFuncAttributeMaxDynamicSharedMemorySize, SM_TOTAL);

    embed_kernel<<<(N_NODES * 32 + 255) / 256, 256>>>(x, type_emb, output_emb, hA);
    wsplit_kernel<<<(NUM_LAYER * 2 * (D * D / 2) + 255) / 256, 256>>>(l1w, l2w, wp);

    // ---- build CSR for both relations (edges constant across layers) ----
    const int NB = (N_NODES + 255) / 256;   // 391
    const int* eis[2] = { e_pos, e_inv };
    for (int rel = 0; rel < 2; rel++) {
        int* rp = rowptr + (size_t)rel * (N_NODES + 1);
        int* cu = cursor + (size_t)rel * N_NODES;
        int* cs = csrsrc + (size_t)rel * N_EDGES;
        int* bs = bsums + (size_t)rel * 512;
        cudaMemsetAsync(rp, 0, (N_NODES + 1) * sizeof(int));
        hist_kernel<<<(N_EDGES + 255) / 256, 256>>>(eis[rel], rp);
        scan1_kernel<<<NB, 256>>>(rp, bs);
        scan2_kernel<<<1, 512>>>(bs, NB);
        scan3_kernel<<<NB, 256>>>(rp, bs);
        cudaMemcpyAsync(cu, rp, N_NODES * sizeof(int), cudaMemcpyDeviceToDevice);
        fill_kernel<<<(N_EDGES + 255) / 256, 256>>>(eis[rel], cu, cs);
    }

    float* h  = hA;
    float* hn = hB;
    const int gemm_grid = (N_NODES + 127) / 128;   // 782

    for (int l = 0; l < NUM_LAYER; l++) {
        for (int rel = 0; rel < 2; rel++) {
            const __nv_bfloat16* wpl = wp + (size_t)(l * 2 + rel) * 4 * D * D;
            const float* b1p = l1b + (size_t)(l * 2 + rel) * D;
            const float* b2p = l2b + (size_t)(l * 2 + rel) * D;
            gin_fused_kernel<<<gemm_grid, 256, SM_TOTAL>>>(
                h,
                rowptr + (size_t)rel * (N_NODES + 1),
                csrsrc + (size_t)rel * N_EDGES,
                wpl, b1p, b2p, hn,
                /*accumulate=*/rel,
                /*relu_out=*/(rel == 1 && l < NUM_LAYER - 1) ? 1 : 0);
        }
        float* tmp = h; h = hn; hn = tmp;
    }

    bounds_kernel<<<1, NGRAPH + 1>>>(batch);
    pool_kernel<<<NGRAPH, D>>>(h, out, out_size);
}

// round 6
// speedup vs baseline: 1.2670x; 1.2670x over previous
#include <cuda_runtime.h>
#include <cuda_bf16.h>
#include <mma.h>
#include <cstdint>
#include <math.h>

using namespace nvcuda;

#define N_NODES 100000
#define N_EDGES 600000
#define D 128
#define NGRAPH 64
#define NUM_LAYER 3

// ---------------- scratch (static device globals; no allocation) ----------------
__device__ float g_bufA[(size_t)N_NODES * D];
__device__ float g_bufB[(size_t)N_NODES * D];
__device__ float g_in0[(size_t)N_NODES * D];
__device__ float g_in1[(size_t)N_NODES * D];
__device__ int   g_gstart[NGRAPH + 1];
// CSR scratch (2 relations)
__device__ int g_rowptr[2][N_NODES + 1];
__device__ int g_cursor[2][N_NODES];
__device__ int g_csrsrc[2][N_EDGES];
__device__ int g_bsums[2][512];
// pre-split weight planes: per (layer,rel): [W1h, W1l, W2h, W2l]
__device__ __nv_bfloat16 g_wplanes[(size_t)NUM_LAYER * 2 * 4 * D * D];

// split fp32 pair into bf16 hi plane + bf16 residual plane (packed bf16x2)
__device__ __forceinline__ void split2(float a, float b, uint32_t& hi, uint32_t& lo) {
    __nv_bfloat16 ha = __float2bfloat16(a), hb = __float2bfloat16(b);
    float ra = a - __bfloat162float(ha);
    float rb = b - __bfloat162float(hb);
    __nv_bfloat162 H; H.x = ha; H.y = hb;
    __nv_bfloat162 L; L.x = __float2bfloat16(ra); L.y = __float2bfloat16(rb);
    hi = *(uint32_t*)&H;
    lo = *(uint32_t*)&L;
}

// ---------------- weight pre-split (runs once per call) --------------------------
__global__ void wsplit_kernel(const float* __restrict__ l1w,
                              const float* __restrict__ l2w,
                              __nv_bfloat16* __restrict__ wp) {
    int i = blockIdx.x * blockDim.x + threadIdx.x;   // over 6 mats * 8192 pairs
    if (i >= NUM_LAYER * 2 * (D * D / 2)) return;
    int mat = i / (D * D / 2);
    int p = i % (D * D / 2);
    float2 a = ((const float2*)l1w)[i];
    float2 b = ((const float2*)l2w)[i];
    uint32_t h, l;
    size_t base = (size_t)mat * 4 * D * D;
    split2(a.x, a.y, h, l);
    ((uint32_t*)&wp[base + 0 * D * D])[p] = h;
    ((uint32_t*)&wp[base + 1 * D * D])[p] = l;
    split2(b.x, b.y, h, l);
    ((uint32_t*)&wp[base + 2 * D * D])[p] = h;
    ((uint32_t*)&wp[base + 3 * D * D])[p] = l;
}

// ---------------- smem layout (bytes) -------------------------------------------
// SSTRIDE = 136 elements (272 B): ldmatrix row phases hit banks 4r mod 32 ->
// conflict-free (288 B stride gave 2-way conflicts on every LDSM).
#define SSTRIDE 136
#define PLANE_BYTES (128 * SSTRIDE * 2)  // 34816
#define SM_B1      0
#define SM_B2      512
#define SM_SCRATCH 1024                  // 8 warps x 256 floats = 8192 B
#define SM_AH      (SM_SCRATCH + 8192)
#define SM_AL      (SM_AH + PLANE_BYTES)
#define SM_W1H     (SM_AL + PLANE_BYTES)
#define SM_W1L     (SM_W1H + PLANE_BYTES)
#define SM_W2H     (SM_W1L + PLANE_BYTES)
#define SM_W2L     (SM_W2H + PLANE_BYTES)
#define SM_TOTAL   (SM_W2L + PLANE_BYTES)   // 218112 bytes

typedef wmma::fragment<wmma::matrix_a, 16, 16, 16, __nv_bfloat16, wmma::row_major> AFrag;
typedef wmma::fragment<wmma::matrix_b, 16, 16, 16, __nv_bfloat16, wmma::row_major> BFrag;
typedef wmma::fragment<wmma::accumulator, 16, 16, 16, float> CFrag;

// ================= fused GIN MLP via bf16 split-precision WMMA ==================
// out (+)= maybe_relu( relu(in@W1 + b1) @ W2 + b2 )
__global__ void __launch_bounds__(256, 1)
gin_mma_kernel(const float* __restrict__ in,
               const __nv_bfloat16* __restrict__ wp,   // 4 planes for this (l,rel)
               const float* __restrict__ b1, const float* __restrict__ b2,
               float* __restrict__ out, int accumulate, int relu_out) {
    extern __shared__ char sm[];
    float* b1s = (float*)(sm + SM_B1);
    float* b2s = (float*)(sm + SM_B2);
    __nv_bfloat16* sAh  = (__nv_bfloat16*)(sm + SM_AH);
    __nv_bfloat16* sAl  = (__nv_bfloat16*)(sm + SM_AL);
    __nv_bfloat16* sW1h = (__nv_bfloat16*)(sm + SM_W1H);
    __nv_bfloat16* sW1l = (__nv_bfloat16*)(sm + SM_W1L);
    __nv_bfloat16* sW2h = (__nv_bfloat16*)(sm + SM_W2H);
    __nv_bfloat16* sW2l = (__nv_bfloat16*)(sm + SM_W2L);

    const int tid = threadIdx.x;
    const int wid = tid >> 5;
    const int lane = tid & 31;
    const int row0 = blockIdx.x * 128;

    if (tid < 128) { b1s[tid] = b1[tid]; b2s[tid] = b2[tid]; }

    // ---- weight planes: pure bf16 uint4 copies (pre-split in gmem) ----
    {
        const uint4* w1hv = (const uint4*)(wp + 0 * D * D);
        const uint4* w1lv = (const uint4*)(wp + 1 * D * D);
        const uint4* w2hv = (const uint4*)(wp + 2 * D * D);
        const uint4* w2lv = (const uint4*)(wp + 3 * D * D);
        for (int i = tid; i < 128 * 16; i += 256) {
            int k = i >> 4, c = i & 15;       // c*8 bf16 offset
            *(uint4*)&sW1h[k * SSTRIDE + c * 8] = w1hv[i];
            *(uint4*)&sW1l[k * SSTRIDE + c * 8] = w1lv[i];
            *(uint4*)&sW2h[k * SSTRIDE + c * 8] = w2hv[i];
            *(uint4*)&sW2l[k * SSTRIDE + c * 8] = w2lv[i];
        }
    }
    // ---- A tile: 128 rows fp32 (pre-aggregated) -> bf16 hi/lo planes ----
    for (int i = tid; i < 128 * 64; i += 256) {
        int m = i >> 6, kp = i & 63;
        int row = row0 + m;
        float2 v = make_float2(0.f, 0.f);
        if (row < N_NODES) v = ((const float2*)(in + (size_t)row * D))[kp];
        uint32_t hi, lo;
        split2(v.x, v.y, hi, lo);
        *(uint32_t*)&sAh[m * SSTRIDE + 2 * kp] = hi;
        *(uint32_t*)&sAl[m * SSTRIDE + 2 * kp] = lo;
    }
    __syncthreads();

    // warp tiling: 4 warps in M (32 rows each), 2 warps in N (64 cols each)
    const int mwarp = wid >> 1;
    const int nwarp = wid & 1;
    const int m0 = mwarp * 32;
    const int n0w = nwarp * 64;
    float* sw = (float*)(sm + SM_SCRATCH) + wid * 256;   // 16x16 fp32 per warp
    const int r = lane >> 1, half = lane & 1;

    CFrag acc[2][4];

    // =================== GEMM1: D1 = A @ W1 (3 split terms) ===================
#pragma unroll
    for (int mt = 0; mt < 2; mt++)
#pragma unroll
        for (int nt = 0; nt < 4; nt++) wmma::fill_fragment(acc[mt][nt], 0.f);

    for (int k = 0; k < 128; k += 16) {
        AFrag ah[2], al[2];
#pragma unroll
        for (int mt = 0; mt < 2; mt++) {
            wmma::load_matrix_sync(ah[mt], sAh + (m0 + mt * 16) * SSTRIDE + k, SSTRIDE);
            wmma::load_matrix_sync(al[mt], sAl + (m0 + mt * 16) * SSTRIDE + k, SSTRIDE);
        }
#pragma unroll
        for (int nt = 0; nt < 4; nt++) {
            BFrag bh, bl;
            wmma::load_matrix_sync(bh, sW1h + k * SSTRIDE + n0w + nt * 16, SSTRIDE);
            wmma::load_matrix_sync(bl, sW1l + k * SSTRIDE + n0w + nt * 16, SSTRIDE);
#pragma unroll
            for (int mt = 0; mt < 2; mt++) {
                wmma::mma_sync(acc[mt][nt], ah[mt], bh, acc[mt][nt]);
                wmma::mma_sync(acc[mt][nt], ah[mt], bl, acc[mt][nt]);
                wmma::mma_sync(acc[mt][nt], al[mt], bh, acc[mt][nt]);
            }
        }
    }
    __syncthreads();   // all warps done reading A planes before overwrite

    // ---- epilogue1: z = relu(D1 + b1) -> re-split into A planes ----
#pragma unroll
    for (int mt = 0; mt < 2; mt++) {
#pragma unroll
        for (int nt = 0; nt < 4; nt++) {
            wmma::store_matrix_sync(sw, acc[mt][nt], 16, wmma::mem_row_major);
            __syncwarp();
#pragma unroll
            for (int q = 0; q < 4; q++) {
                int c0 = half * 8 + 2 * q;
                int n0 = n0w + nt * 16 + c0;
                float z0 = fmaxf(sw[r * 16 + c0]     + b1s[n0],     0.f);
                float z1 = fmaxf(sw[r * 16 + c0 + 1] + b1s[n0 + 1], 0.f);
                uint32_t hi, lo;
                split2(z0, z1, hi, lo);
                int mrow = m0 + mt * 16 + r;
                *(uint32_t*)&sAh[mrow * SSTRIDE + n0] = hi;
                *(uint32_t*)&sAl[mrow * SSTRIDE + n0] = lo;
            }
            __syncwarp();
        }
    }
    __syncthreads();   // full Z tile visible to all warps

    // =================== GEMM2: D2 = Z @ W2 (3 split terms) ===================
#pragma unroll
    for (int mt = 0; mt < 2; mt++)
#pragma unroll
        for (int nt = 0; nt < 4; nt++) wmma::fill_fragment(acc[mt][nt], 0.f);

    for (int k = 0; k < 128; k += 16) {
        AFrag ah[2], al[2];
#pragma unroll
        for (int mt = 0; mt < 2; mt++) {
            wmma::load_matrix_sync(ah[mt], sAh + (m0 + mt * 16) * SSTRIDE + k, SSTRIDE);
            wmma::load_matrix_sync(al[mt], sAl + (m0 + mt * 16) * SSTRIDE + k, SSTRIDE);
        }
#pragma unroll
        for (int nt = 0; nt < 4; nt++) {
            BFrag bh, bl;
            wmma::load_matrix_sync(bh, sW2h + k * SSTRIDE + n0w + nt * 16, SSTRIDE);
            wmma::load_matrix_sync(bl, sW2l + k * SSTRIDE + n0w + nt * 16, SSTRIDE);
#pragma unroll
            for (int mt = 0; mt < 2; mt++) {
                wmma::mma_sync(acc[mt][nt], ah[mt], bh, acc[mt][nt]);
                wmma::mma_sync(acc[mt][nt], ah[mt], bl, acc[mt][nt]);
                wmma::mma_sync(acc[mt][nt], al[mt], bh, acc[mt][nt]);
            }
        }
    }

    // ---- epilogue2: out (+)= maybe_relu(D2 + b2) ----
#pragma unroll
    for (int mt = 0; mt < 2; mt++) {
        const int row = row0 + m0 + mt * 16 + r;
#pragma unroll
        for (int nt = 0; nt < 4; nt++) {
            wmma::store_matrix_sync(sw, acc[mt][nt], 16, wmma::mem_row_major);
            __syncwarp();
            if (row < N_NODES) {
                int n0 = nt * 16 + n0w + half * 8;
                float* op = out + (size_t)row * D + n0;
                float v[8];
#pragma unroll
                for (int j = 0; j < 8; j++) v[j] = sw[r * 16 + half * 8 + j] + b2s[n0 + j];
                if (accumulate) {
                    float4 o0 = *(const float4*)(op);
                    float4 o1 = *(const float4*)(op + 4);
                    v[0] += o0.x; v[1] += o0.y; v[2] += o0.z; v[3] += o0.w;
                    v[4] += o1.x; v[5] += o1.y; v[6] += o1.z; v[7] += o1.w;
                }
                if (relu_out) {
#pragma unroll
                    for (int j = 0; j < 8; j++) v[j] = fmaxf(v[j], 0.f);
                }
                *(float4*)(op)     = make_float4(v[0], v[1], v[2], v[3]);
                *(float4*)(op + 4) = make_float4(v[4], v[5], v[6], v[7]);
            }
            __syncwarp();
        }
    }
}

// ---------------- node input embedding ------------------------------------------
__global__ void embed_kernel(const int* __restrict__ x,
                             const float* __restrict__ type_emb,
                             const float* __restrict__ output_emb,
                             float* __restrict__ h) {
    int tid = blockIdx.x * blockDim.x + threadIdx.x;
    int node = tid >> 5;
    int c = tid & 31;
    if (node >= N_NODES) return;
    int t = x[node * 2 + 0];
    int o = x[node * 2 + 1];
    float4 a = ((const float4*)(type_emb + (size_t)t * D))[c];
    float4 b = ((const float4*)(output_emb + (size_t)o * D))[c];
    ((float4*)(h + (size_t)node * D))[c] =
        make_float4(a.x + b.x, a.y + b.y, a.z + b.z, a.w + b.w);
}

// ---------------- CSR build -------------------------------------------------------
__global__ void hist_kernel(const int* __restrict__ ei, int* __restrict__ rowptr) {
    int e = blockIdx.x * blockDim.x + threadIdx.x;
    if (e >= N_EDGES) return;
    atomicAdd(&rowptr[ei[N_EDGES + e] + 1], 1);
}
__global__ void scan1_kernel(int* __restrict__ rowptr, int* __restrict__ bsums) {
    __shared__ int s[256];
    int idx = blockIdx.x * 256 + threadIdx.x;
    int v = (idx < N_NODES) ? rowptr[idx + 1] : 0;
    s[threadIdx.x] = v;
    __syncthreads();
#pragma unroll
    for (int o = 1; o < 256; o <<= 1) {
        int t = (threadIdx.x >= o) ? s[threadIdx.x - o] : 0;
        __syncthreads();
        s[threadIdx.x] += t;
        __syncthreads();
    }
    if (idx < N_NODES) rowptr[idx + 1] = s[threadIdx.x];
    if (threadIdx.x == 255) bsums[blockIdx.x] = s[255];
}
__global__ void scan2_kernel(int* __restrict__ bsums, int nb) {
    __shared__ int s[512];
    int t = threadIdx.x;
    int v = (t < nb) ? bsums[t] : 0;
    s[t] = v;
    __syncthreads();
#pragma unroll
    for (int o = 1; o < 512; o <<= 1) {
        int x = (t >= o) ? s[t - o] : 0;
        __syncthreads();
        s[t] += x;
        __syncthreads();
    }
    if (t < nb) bsums[t] = s[t] - v;   // exclusive prefix
}
__global__ void scan3_kernel(int* __restrict__ rowptr, const int* __restrict__ bsums) {
    int idx = blockIdx.x * 256 + threadIdx.x;
    if (idx < N_NODES) rowptr[idx + 1] += bsums[blockIdx.x];
}
__global__ void fill_kernel(const int* __restrict__ ei, int* __restrict__ cursor,
                            int* __restrict__ csrsrc) {
    int e = blockIdx.x * blockDim.x + threadIdx.x;
    if (e >= N_EDGES) return;
    int src = ei[e];
    int dst = ei[N_EDGES + e];
    int pos = atomicAdd(&cursor[dst], 1);
    csrsrc[pos] = src;
}

// ---------------- gather aggregation: agg[n] = h[n] + sum_{src in N(n)} h[src] ---
__global__ void gather_kernel(const float* __restrict__ h,
                              const int* __restrict__ rowptr,
                              const int* __restrict__ csrsrc,
                              float* __restrict__ agg) {
    int warp = (blockIdx.x * blockDim.x + threadIdx.x) >> 5;
    int lane = threadIdx.x & 31;
    if (warp >= N_NODES) return;
    int s = rowptr[warp], e = rowptr[warp + 1];
    float4 acc = ((const float4*)(h + (size_t)warp * D))[lane];
    for (int i = s; i < e; i++) {
        int src = __ldg(&csrsrc[i]);
        float4 v = ((const float4*)(h + (size_t)src * D))[lane];
        acc.x += v.x; acc.y += v.y; acc.z += v.z; acc.w += v.w;
    }
    ((float4*)(agg + (size_t)warp * D))[lane] = acc;
}

// ---------------- graph segment boundaries ---------------------------------------
__global__ void bounds_kernel(const int* __restrict__ batch) {
    int g = threadIdx.x;
    if (g > NGRAPH) return;
    int lo = 0, hi = N_NODES;
    while (lo < hi) {
        int mid = (lo + hi) >> 1;
        if (batch[mid] < g) lo = mid + 1; else hi = mid;
    }
    g_gstart[g] = lo;
}

// ---------------- pooling --------------------------------------------------------
__global__ void pool_kernel(const float* __restrict__ h, float* __restrict__ out,
                            int out_size) {
    int b = blockIdx.x;
    int c = threadIdx.x;
    int s = g_gstart[b], e = g_gstart[b + 1];
    float s0 = 0.f, s1 = 0.f, s2 = 0.f, s3 = 0.f;
    float mx = -INFINITY, mn = INFINITY;
    int r = s;
    for (; r + 4 <= e; r += 4) {
        float v0 = h[(size_t)(r + 0) * D + c];
        float v1 = h[(size_t)(r + 1) * D + c];
        float v2 = h[(size_t)(r + 2) * D + c];
        float v3 = h[(size_t)(r + 3) * D + c];
        s0 += v0; s1 += v1; s2 += v2; s3 += v3;
        mx = fmaxf(mx, fmaxf(fmaxf(v0, v1), fmaxf(v2, v3)));
        mn = fminf(mn, fminf(fminf(v0, v1), fminf(v2, v3)));
    }
    for (; r < e; r++) {
        float v = h[(size_t)r * D + c];
        s0 += v; mx = fmaxf(mx, v); mn = fminf(mn, v);
    }
    float sum = (s0 + s1) + (s2 + s3);
    float cnt = (float)(e - s);
    float mean = sum / fmaxf(cnt, 1.f);
    float vals[4] = { sum, mean, mx, mn };
#pragma unroll
    for (int a = 0; a < 4; a++) {
        int m = a * D + c;
        out[b * 512 + (m & 3) * 128 + (m >> 2)] = vals[a];
    }
    if (c < 4) {
        int idx = NGRAPH * 4 * D + b * 4 + c;
        if (idx < out_size) out[idx] = 1.0f;
    }
}

// ---------------- launch ---------------------------------------------------------
extern "C" void kernel_launch(void* const* d_in, const int* in_sizes, int n_in,
                              void* d_out, int out_size) {
    const int*   x          = (const int*)d_in[0];
    const int*   e_pos      = (const int*)d_in[1];
    const int*   e_inv      = (const int*)d_in[2];
    const int*   batch      = (const int*)d_in[3];
    const float* type_emb   = (const float*)d_in[4];
    const float* output_emb = (const float*)d_in[5];
    const float* l1w        = (const float*)d_in[6];
    const float* l1b        = (const float*)d_in[7];
    const float* l2w        = (const float*)d_in[8];
    const float* l2b        = (const float*)d_in[9];
    float* out = (float*)d_out;

    float *hA, *hB, *i0, *i1;
    int *rowptr, *cursor, *csrsrc, *bsums;
    __nv_bfloat16* wp;
    cudaGetSymbolAddress((void**)&hA, g_bufA);
    cudaGetSymbolAddress((void**)&hB, g_bufB);
    cudaGetSymbolAddress((void**)&i0, g_in0);
    cudaGetSymbolAddress((void**)&i1, g_in1);
    cudaGetSymbolAddress((void**)&rowptr, g_rowptr);
    cudaGetSymbolAddress((void**)&cursor, g_cursor);
    cudaGetSymbolAddress((void**)&csrsrc, g_csrsrc);
    cudaGetSymbolAddress((void**)&bsums, g_bsums);
    cudaGetSymbolAddress((void**)&wp, g_wplanes);

    cudaFuncSetAttribute(gin_mma_kernel,
                         cudaFuncAttributeMaxDynamicSharedMemorySize, SM_TOTAL);

    embed_kernel<<<(N_NODES * 32 + 255) / 256, 256>>>(x, type_emb, output_emb, hA);
    wsplit_kernel<<<(NUM_LAYER * 2 * (D * D / 2) + 255) / 256, 256>>>(l1w, l2w, wp);

    // ---- build CSR for both relations (edges constant across layers) ----
    const int NB = (N_NODES + 255) / 256;   // 391
    const int* eis[2] = { e_pos, e_inv };
    for (int rel = 0; rel < 2; rel++) {
        int* rp = rowptr + (size_t)rel * (N_NODES + 1);
        int* cu = cursor + (size_t)rel * N_NODES;
        int* cs = csrsrc + (size_t)rel * N_EDGES;
        int* bs = bsums + (size_t)rel * 512;
        cudaMemsetAsync(rp, 0, (N_NODES + 1) * sizeof(int));
        hist_kernel<<<(N_EDGES + 255) / 256, 256>>>(eis[rel], rp);
        scan1_kernel<<<NB, 256>>>(rp, bs);
        scan2_kernel<<<1, 512>>>(bs, NB);
        scan3_kernel<<<NB, 256>>>(rp, bs);
        cudaMemcpyAsync(cu, rp, N_NODES * sizeof(int), cudaMemcpyDeviceToDevice);
        fill_kernel<<<(N_EDGES + 255) / 256, 256>>>(eis[rel], cu, cs);
    }

    float* h  = hA;
    float* hn = hB;
    const int gemm_grid = (N_NODES + 127) / 128;   // 782
    const int gather_grid = (N_NODES * 32 + 255) / 256;

    for (int l = 0; l < NUM_LAYER; l++) {
        gather_kernel<<<gather_grid, 256>>>(h, rowptr, csrsrc, i0);
        gather_kernel<<<gather_grid, 256>>>(h, rowptr + (N_NODES + 1),
                                            csrsrc + N_EDGES, i1);

        for (int rel = 0; rel < 2; rel++) {
            const __nv_bfloat16* wpl = wp + (size_t)(l * 2 + rel) * 4 * D * D;
            const float* b1p = l1b + (size_t)(l * 2 + rel) * D;
            const float* b2p = l2b + (size_t)(l * 2 + rel) * D;
            gin_mma_kernel<<<gemm_grid, 256, SM_TOTAL>>>(
                rel == 0 ? i0 : i1, wpl, b1p, b2p, hn,
                /*accumulate=*/rel,
                /*relu_out=*/(rel == 1 && l < NUM_LAYER - 1) ? 1 : 0);
        }
        float* tmp = h; h = hn; hn = tmp;
    }

    bounds_kernel<<<1, NGRAPH + 1>>>(batch);
    pool_kernel<<<NGRAPH, D>>>(h, out, out_size);
}

// round 7
// speedup vs baseline: 1.3679x; 1.0797x over previous
#include <cuda_runtime.h>
#include <cuda_bf16.h>
#include <mma.h>
#include <cstdint>
#include <math.h>

using namespace nvcuda;

#define N_NODES 100000
#define N_EDGES 600000
#define D 128
#define NGRAPH 64
#define NUM_LAYER 3

// ---------------- scratch (static device globals; no allocation) ----------------
__device__ float g_bufA[(size_t)N_NODES * D];
__device__ float g_bufB[(size_t)N_NODES * D];
__device__ float g_in0[(size_t)N_NODES * D];
__device__ float g_in1[(size_t)N_NODES * D];
__device__ int   g_gstart[NGRAPH + 1];
// CSR scratch (2 relations)
__device__ int g_rowptr[2][N_NODES + 1];
__device__ int g_cursor[2][N_NODES];
__device__ int g_csrsrc[2][N_EDGES];
__device__ int g_bsums[2][512];
// pre-split weight planes: per (layer,rel): [W1h, W1l, W2h, W2l]
__device__ __nv_bfloat16 g_wplanes[(size_t)NUM_LAYER * 2 * 4 * D * D];

// split fp32 pair into bf16 hi plane + bf16 residual plane (packed bf16x2)
__device__ __forceinline__ void split2(float a, float b, uint32_t& hi, uint32_t& lo) {
    __nv_bfloat16 ha = __float2bfloat16(a), hb = __float2bfloat16(b);
    float ra = a - __bfloat162float(ha);
    float rb = b - __bfloat162float(hb);
    __nv_bfloat162 H; H.x = ha; H.y = hb;
    __nv_bfloat162 L; L.x = __float2bfloat16(ra); L.y = __float2bfloat16(rb);
    hi = *(uint32_t*)&H;
    lo = *(uint32_t*)&L;
}

// ---------------- weight pre-split (runs once per call) --------------------------
__global__ void wsplit_kernel(const float* __restrict__ l1w,
                              const float* __restrict__ l2w,
                              __nv_bfloat16* __restrict__ wp) {
    int i = blockIdx.x * blockDim.x + threadIdx.x;   // over 6 mats * 8192 pairs
    if (i >= NUM_LAYER * 2 * (D * D / 2)) return;
    int mat = i / (D * D / 2);
    int p = i % (D * D / 2);
    float2 a = ((const float2*)l1w)[i];
    float2 b = ((const float2*)l2w)[i];
    uint32_t h, l;
    size_t base = (size_t)mat * 4 * D * D;
    split2(a.x, a.y, h, l);
    ((uint32_t*)&wp[base + 0 * D * D])[p] = h;
    ((uint32_t*)&wp[base + 1 * D * D])[p] = l;
    split2(b.x, b.y, h, l);
    ((uint32_t*)&wp[base + 2 * D * D])[p] = h;
    ((uint32_t*)&wp[base + 3 * D * D])[p] = l;
}

// ---------------- smem layout (bytes) -------------------------------------------
// SSTRIDE = 136 elements (272 B rows): conflict-free ldmatrix phases.
#define SSTRIDE 136
#define PLANE_BYTES (128 * SSTRIDE * 2)  // 34816
#define SM_B1      0                     // 2 x 128 floats (per relation)
#define SM_B2S     1024                  // combined b2 sum, 128 floats
#define SM_SCRATCH 1536                  // 8 warps x 256 floats = 8192 B
#define SM_AH      (SM_SCRATCH + 8192)
#define SM_AL      (SM_AH + PLANE_BYTES)
#define SM_W1H     (SM_AL + PLANE_BYTES)
#define SM_W1L     (SM_W1H + PLANE_BYTES)
#define SM_W2H     (SM_W1L + PLANE_BYTES)
#define SM_W2L     (SM_W2H + PLANE_BYTES)
#define SM_TOTAL   (SM_W2L + PLANE_BYTES)   // 218624 bytes

typedef wmma::fragment<wmma::matrix_a, 16, 16, 16, __nv_bfloat16, wmma::row_major> AFrag;
typedef wmma::fragment<wmma::matrix_b, 16, 16, 16, __nv_bfloat16, wmma::row_major> BFrag;
typedef wmma::fragment<wmma::accumulator, 16, 16, 16, float> CFrag;

// ==== merged dual-relation GIN layer:
//   out = f( [relu(agg0@W1_0+b1_0)@W2_0 + b2_0] + [relu(agg1@W1_1+b1_1)@W2_1 + b2_1] )
__global__ void __launch_bounds__(256, 1)
gin_dual_kernel(const float* __restrict__ agg0, const float* __restrict__ agg1,
                const __nv_bfloat16* __restrict__ wp,   // layer base: 8 planes
                const float* __restrict__ b1,           // [2][128] (rel0, rel1)
                const float* __restrict__ b2,           // [2][128]
                float* __restrict__ out, int relu_out) {
    extern __shared__ char sm[];
    float* b1s = (float*)(sm + SM_B1);      // [2][128]
    float* b2s = (float*)(sm + SM_B2S);     // combined
    __nv_bfloat16* sAh  = (__nv_bfloat16*)(sm + SM_AH);
    __nv_bfloat16* sAl  = (__nv_bfloat16*)(sm + SM_AL);
    __nv_bfloat16* sW1h = (__nv_bfloat16*)(sm + SM_W1H);
    __nv_bfloat16* sW1l = (__nv_bfloat16*)(sm + SM_W1L);
    __nv_bfloat16* sW2h = (__nv_bfloat16*)(sm + SM_W2H);
    __nv_bfloat16* sW2l = (__nv_bfloat16*)(sm + SM_W2L);

    const int tid = threadIdx.x;
    const int wid = tid >> 5;
    const int lane = tid & 31;
    const int row0 = blockIdx.x * 128;

    if (tid < 128) {
        b1s[tid]       = b1[tid];
        b1s[128 + tid] = b1[128 + tid];
        b2s[tid]       = b2[tid] + b2[128 + tid];
    }

    // warp tiling: 4 warps in M (32 rows each), 2 warps in N (64 cols each)
    const int mwarp = wid >> 1;
    const int nwarp = wid & 1;
    const int m0 = mwarp * 32;
    const int n0w = nwarp * 64;
    float* sw = (float*)(sm + SM_SCRATCH) + wid * 256;
    const int r = lane >> 1, half = lane & 1;

    CFrag accT[2][4];   // running sum over relations (D2_0 + D2_1)
#pragma unroll
    for (int mt = 0; mt < 2; mt++)
#pragma unroll
        for (int nt = 0; nt < 4; nt++) wmma::fill_fragment(accT[mt][nt], 0.f);

#pragma unroll
    for (int rel = 0; rel < 2; rel++) {
        const float* in = (rel == 0) ? agg0 : agg1;
        const __nv_bfloat16* wpr = wp + (size_t)rel * 4 * D * D;
        if (rel == 1) __syncthreads();   // done reading prev W/A planes

        // ---- weight planes: bf16 uint4 copies ----
        {
            const uint4* w1hv = (const uint4*)(wpr + 0 * D * D);
            const uint4* w1lv = (const uint4*)(wpr + 1 * D * D);
            const uint4* w2hv = (const uint4*)(wpr + 2 * D * D);
            const uint4* w2lv = (const uint4*)(wpr + 3 * D * D);
            for (int i = tid; i < 128 * 16; i += 256) {
                int k = i >> 4, c = i & 15;
                *(uint4*)&sW1h[k * SSTRIDE + c * 8] = w1hv[i];
                *(uint4*)&sW1l[k * SSTRIDE + c * 8] = w1lv[i];
                *(uint4*)&sW2h[k * SSTRIDE + c * 8] = w2hv[i];
                *(uint4*)&sW2l[k * SSTRIDE + c * 8] = w2lv[i];
            }
        }
        // ---- A tile: 128 rows fp32 (pre-aggregated) -> bf16 hi/lo planes ----
        for (int i = tid; i < 128 * 64; i += 256) {
            int m = i >> 6, kp = i & 63;
            int row = row0 + m;
            float2 v = make_float2(0.f, 0.f);
            if (row < N_NODES) v = ((const float2*)(in + (size_t)row * D))[kp];
            uint32_t hi, lo;
            split2(v.x, v.y, hi, lo);
            *(uint32_t*)&sAh[m * SSTRIDE + 2 * kp] = hi;
            *(uint32_t*)&sAl[m * SSTRIDE + 2 * kp] = lo;
        }
        __syncthreads();

        // ------- GEMM1: accW = A @ W1 (3 split terms) -------
        CFrag accW[2][4];
#pragma unroll
        for (int mt = 0; mt < 2; mt++)
#pragma unroll
            for (int nt = 0; nt < 4; nt++) wmma::fill_fragment(accW[mt][nt], 0.f);

        for (int k = 0; k < 128; k += 16) {
            AFrag ah[2], al[2];
#pragma unroll
            for (int mt = 0; mt < 2; mt++) {
                wmma::load_matrix_sync(ah[mt], sAh + (m0 + mt * 16) * SSTRIDE + k, SSTRIDE);
                wmma::load_matrix_sync(al[mt], sAl + (m0 + mt * 16) * SSTRIDE + k, SSTRIDE);
            }
#pragma unroll
            for (int nt = 0; nt < 4; nt++) {
                BFrag bh, bl;
                wmma::load_matrix_sync(bh, sW1h + k * SSTRIDE + n0w + nt * 16, SSTRIDE);
                wmma::load_matrix_sync(bl, sW1l + k * SSTRIDE + n0w + nt * 16, SSTRIDE);
#pragma unroll
                for (int mt = 0; mt < 2; mt++) {
                    wmma::mma_sync(accW[mt][nt], ah[mt], bh, accW[mt][nt]);
                    wmma::mma_sync(accW[mt][nt], ah[mt], bl, accW[mt][nt]);
                    wmma::mma_sync(accW[mt][nt], al[mt], bh, accW[mt][nt]);
                }
            }
        }
        __syncthreads();   // all warps done reading A planes before overwrite

        // ------- epilogue1: z = relu(accW + b1[rel]) -> A planes -------
        const float* b1r = b1s + rel * 128;
#pragma unroll
        for (int mt = 0; mt < 2; mt++) {
#pragma unroll
            for (int nt = 0; nt < 4; nt++) {
                wmma::store_matrix_sync(sw, accW[mt][nt], 16, wmma::mem_row_major);
                __syncwarp();
#pragma unroll
                for (int q = 0; q < 4; q++) {
                    int c0 = half * 8 + 2 * q;
                    int n0 = n0w + nt * 16 + c0;
                    float z0 = fmaxf(sw[r * 16 + c0]     + b1r[n0],     0.f);
                    float z1 = fmaxf(sw[r * 16 + c0 + 1] + b1r[n0 + 1], 0.f);
                    uint32_t hi, lo;
                    split2(z0, z1, hi, lo);
                    int mrow = m0 + mt * 16 + r;
                    *(uint32_t*)&sAh[mrow * SSTRIDE + n0] = hi;
                    *(uint32_t*)&sAl[mrow * SSTRIDE + n0] = lo;
                }
                __syncwarp();
            }
        }
        __syncthreads();   // full Z tile visible

        // ------- GEMM2: accT += Z @ W2 (3 split terms) -------
        for (int k = 0; k < 128; k += 16) {
            AFrag ah[2], al[2];
#pragma unroll
            for (int mt = 0; mt < 2; mt++) {
                wmma::load_matrix_sync(ah[mt], sAh + (m0 + mt * 16) * SSTRIDE + k, SSTRIDE);
                wmma::load_matrix_sync(al[mt], sAl + (m0 + mt * 16) * SSTRIDE + k, SSTRIDE);
            }
#pragma unroll
            for (int nt = 0; nt < 4; nt++) {
                BFrag bh, bl;
                wmma::load_matrix_sync(bh, sW2h + k * SSTRIDE + n0w + nt * 16, SSTRIDE);
                wmma::load_matrix_sync(bl, sW2l + k * SSTRIDE + n0w + nt * 16, SSTRIDE);
#pragma unroll
                for (int mt = 0; mt < 2; mt++) {
                    wmma::mma_sync(accT[mt][nt], ah[mt], bh, accT[mt][nt]);
                    wmma::mma_sync(accT[mt][nt], ah[mt], bl, accT[mt][nt]);
                    wmma::mma_sync(accT[mt][nt], al[mt], bh, accT[mt][nt]);
                }
            }
        }
    }

    // ---- final epilogue: out = maybe_relu(accT + b2_0 + b2_1) ----
#pragma unroll
    for (int mt = 0; mt < 2; mt++) {
        const int row = row0 + m0 + mt * 16 + r;
#pragma unroll
        for (int nt = 0; nt < 4; nt++) {
            wmma::store_matrix_sync(sw, accT[mt][nt], 16, wmma::mem_row_major);
            __syncwarp();
            if (row < N_NODES) {
                int n0 = n0w + nt * 16 + half * 8;
                float* op = out + (size_t)row * D + n0;
                float v[8];
#pragma unroll
                for (int j = 0; j < 8; j++) v[j] = sw[r * 16 + half * 8 + j] + b2s[n0 + j];
                if (relu_out) {
#pragma unroll
                    for (int j = 0; j < 8; j++) v[j] = fmaxf(v[j], 0.f);
                }
                *(float4*)(op)     = make_float4(v[0], v[1], v[2], v[3]);
                *(float4*)(op + 4) = make_float4(v[4], v[5], v[6], v[7]);
            }
            __syncwarp();
        }
    }
}

// ---------------- node input embedding ------------------------------------------
__global__ void embed_kernel(const int* __restrict__ x,
                             const float* __restrict__ type_emb,
                             const float* __restrict__ output_emb,
                             float* __restrict__ h) {
    int tid = blockIdx.x * blockDim.x + threadIdx.x;
    int node = tid >> 5;
    int c = tid & 31;
    if (node >= N_NODES) return;
    int t = x[node * 2 + 0];
    int o = x[node * 2 + 1];
    float4 a = ((const float4*)(type_emb + (size_t)t * D))[c];
    float4 b = ((const float4*)(output_emb + (size_t)o * D))[c];
    ((float4*)(h + (size_t)node * D))[c] =
        make_float4(a.x + b.x, a.y + b.y, a.z + b.z, a.w + b.w);
}

// ---------------- CSR build -------------------------------------------------------
__global__ void hist_kernel(const int* __restrict__ ei, int* __restrict__ rowptr) {
    int e = blockIdx.x * blockDim.x + threadIdx.x;
    if (e >= N_EDGES) return;
    atomicAdd(&rowptr[ei[N_EDGES + e] + 1], 1);
}
__global__ void scan1_kernel(int* __restrict__ rowptr, int* __restrict__ bsums) {
    __shared__ int s[256];
    int idx = blockIdx.x * 256 + threadIdx.x;
    int v = (idx < N_NODES) ? rowptr[idx + 1] : 0;
    s[threadIdx.x] = v;
    __syncthreads();
#pragma unroll
    for (int o = 1; o < 256; o <<= 1) {
        int t = (threadIdx.x >= o) ? s[threadIdx.x - o] : 0;
        __syncthreads();
        s[threadIdx.x] += t;
        __syncthreads();
    }
    if (idx < N_NODES) rowptr[idx + 1] = s[threadIdx.x];
    if (threadIdx.x == 255) bsums[blockIdx.x] = s[255];
}
__global__ void scan2_kernel(int* __restrict__ bsums, int nb) {
    __shared__ int s[512];
    int t = threadIdx.x;
    int v = (t < nb) ? bsums[t] : 0;
    s[t] = v;
    __syncthreads();
#pragma unroll
    for (int o = 1; o < 512; o <<= 1) {
        int x = (t >= o) ? s[t - o] : 0;
        __syncthreads();
        s[t] += x;
        __syncthreads();
    }
    if (t < nb) bsums[t] = s[t] - v;   // exclusive prefix
}
__global__ void scan3_kernel(int* __restrict__ rowptr, const int* __restrict__ bsums) {
    int idx = blockIdx.x * 256 + threadIdx.x;
    if (idx < N_NODES) rowptr[idx + 1] += bsums[blockIdx.x];
}
__global__ void fill_kernel(const int* __restrict__ ei, int* __restrict__ cursor,
                            int* __restrict__ csrsrc) {
    int e = blockIdx.x * blockDim.x + threadIdx.x;
    if (e >= N_EDGES) return;
    int src = ei[e];
    int dst = ei[N_EDGES + e];
    int pos = atomicAdd(&cursor[dst], 1);
    csrsrc[pos] = src;
}

// ---- dual gather: agg_r[n] = h[n] + sum_{src in N_r(n)} h[src], r=0,1 ----------
__global__ void gather2_kernel(const float* __restrict__ h,
                               const int* __restrict__ rp0,
                               const int* __restrict__ cs0,
                               const int* __restrict__ rp1,
                               const int* __restrict__ cs1,
                               float* __restrict__ agg0,
                               float* __restrict__ agg1) {
    int warp = (blockIdx.x * blockDim.x + threadIdx.x) >> 5;
    int lane = threadIdx.x & 31;
    if (warp >= N_NODES) return;
    float4 base = ((const float4*)(h + (size_t)warp * D))[lane];
    {
        int s = rp0[warp], e = rp0[warp + 1];
        float4 acc = base;
        for (int i = s; i < e; i++) {
            int src = __ldg(&cs0[i]);
            float4 v = ((const float4*)(h + (size_t)src * D))[lane];
            acc.x += v.x; acc.y += v.y; acc.z += v.z; acc.w += v.w;
        }
        ((float4*)(agg0 + (size_t)warp * D))[lane] = acc;
    }
    {
        int s = rp1[warp], e = rp1[warp + 1];
        float4 acc = base;
        for (int i = s; i < e; i++) {
            int src = __ldg(&cs1[i]);
            float4 v = ((const float4*)(h + (size_t)src * D))[lane];
            acc.x += v.x; acc.y += v.y; acc.z += v.z; acc.w += v.w;
        }
        ((float4*)(agg1 + (size_t)warp * D))[lane] = acc;
    }
}

// ---------------- graph segment boundaries ---------------------------------------
__global__ void bounds_kernel(const int* __restrict__ batch) {
    int g = threadIdx.x;
    if (g > NGRAPH) return;
    int lo = 0, hi = N_NODES;
    while (lo < hi) {
        int mid = (lo + hi) >> 1;
        if (batch[mid] < g) lo = mid + 1; else hi = mid;
    }
    g_gstart[g] = lo;
}

// ---------------- pooling --------------------------------------------------------
__global__ void pool_kernel(const float* __restrict__ h, float* __restrict__ out,
                            int out_size) {
    int b = blockIdx.x;
    int c = threadIdx.x;
    int s = g_gstart[b], e = g_gstart[b + 1];
    float s0 = 0.f, s1 = 0.f, s2 = 0.f, s3 = 0.f;
    float mx = -INFINITY, mn = INFINITY;
    int r = s;
    for (; r + 4 <= e; r += 4) {
        float v0 = h[(size_t)(r + 0) * D + c];
        float v1 = h[(size_t)(r + 1) * D + c];
        float v2 = h[(size_t)(r + 2) * D + c];
        float v3 = h[(size_t)(r + 3) * D + c];
        s0 += v0; s1 += v1; s2 += v2; s3 += v3;
        mx = fmaxf(mx, fmaxf(fmaxf(v0, v1), fmaxf(v2, v3)));
        mn = fminf(mn, fminf(fminf(v0, v1), fminf(v2, v3)));
    }
    for (; r < e; r++) {
        float v = h[(size_t)r * D + c];
        s0 += v; mx = fmaxf(mx, v); mn = fminf(mn, v);
    }
    float sum = (s0 + s1) + (s2 + s3);
    float cnt = (float)(e - s);
    float mean = sum / fmaxf(cnt, 1.f);
    float vals[4] = { sum, mean, mx, mn };
#pragma unroll
    for (int a = 0; a < 4; a++) {
        int m = a * D + c;
        out[b * 512 + (m & 3) * 128 + (m >> 2)] = vals[a];
    }
    if (c < 4) {
        int idx = NGRAPH * 4 * D + b * 4 + c;
        if (idx < out_size) out[idx] = 1.0f;
    }
}

// ---------------- launch ---------------------------------------------------------
extern "C" void kernel_launch(void* const* d_in, const int* in_sizes, int n_in,
                              void* d_out, int out_size) {
    const int*   x          = (const int*)d_in[0];
    const int*   e_pos      = (const int*)d_in[1];
    const int*   e_inv      = (const int*)d_in[2];
    const int*   batch      = (const int*)d_in[3];
    const float* type_emb   = (const float*)d_in[4];
    const float* output_emb = (const float*)d_in[5];
    const float* l1w        = (const float*)d_in[6];
    const float* l1b        = (const float*)d_in[7];
    const float* l2w        = (const float*)d_in[8];
    const float* l2b        = (const float*)d_in[9];
    float* out = (float*)d_out;

    float *hA, *hB, *i0, *i1;
    int *rowptr, *cursor, *csrsrc, *bsums;
    __nv_bfloat16* wp;
    cudaGetSymbolAddress((void**)&hA, g_bufA);
    cudaGetSymbolAddress((void**)&hB, g_bufB);
    cudaGetSymbolAddress((void**)&i0, g_in0);
    cudaGetSymbolAddress((void**)&i1, g_in1);
    cudaGetSymbolAddress((void**)&rowptr, g_rowptr);
    cudaGetSymbolAddress((void**)&cursor, g_cursor);
    cudaGetSymbolAddress((void**)&csrsrc, g_csrsrc);
    cudaGetSymbolAddress((void**)&bsums, g_bsums);
    cudaGetSymbolAddress((void**)&wp, g_wplanes);

    cudaFuncSetAttribute(gin_dual_kernel,
                         cudaFuncAttributeMaxDynamicSharedMemorySize, SM_TOTAL);

    embed_kernel<<<(N_NODES * 32 + 255) / 256, 256>>>(x, type_emb, output_emb, hA);
    wsplit_kernel<<<(NUM_LAYER * 2 * (D * D / 2) + 255) / 256, 256>>>(l1w, l2w, wp);

    // ---- build CSR for both relations (edges constant across layers) ----
    const int NB = (N_NODES + 255) / 256;   // 391
    const int* eis[2] = { e_pos, e_inv };
    for (int rel = 0; rel < 2; rel++) {
        int* rp = rowptr + (size_t)rel * (N_NODES + 1);
        int* cu = cursor + (size_t)rel * N_NODES;
        int* cs = csrsrc + (size_t)rel * N_EDGES;
        int* bs = bsums + (size_t)rel * 512;
        cudaMemsetAsync(rp, 0, (N_NODES + 1) * sizeof(int));
        hist_kernel<<<(N_EDGES + 255) / 256, 256>>>(eis[rel], rp);
        scan1_kernel<<<NB, 256>>>(rp, bs);
        scan2_kernel<<<1, 512>>>(bs, NB);
        scan3_kernel<<<NB, 256>>>(rp, bs);
        cudaMemcpyAsync(cu, rp, N_NODES * sizeof(int), cudaMemcpyDeviceToDevice);
        fill_kernel<<<(N_EDGES + 255) / 256, 256>>>(eis[rel], cu, cs);
    }

    float* h  = hA;
    float* hn = hB;
    const int gemm_grid = (N_NODES + 127) / 128;   // 782
    const int gather_grid = (N_NODES * 32 + 255) / 256;

    for (int l = 0; l < NUM_LAYER; l++) {
        gather2_kernel<<<gather_grid, 256>>>(h,
                                             rowptr, csrsrc,
                                             rowptr + (N_NODES + 1), csrsrc + N_EDGES,
                                             i0, i1);

        const __nv_bfloat16* wpl = wp + (size_t)l * 2 * 4 * D * D;
        const float* b1p = l1b + (size_t)l * 2 * D;   // [2][128]
        const float* b2p = l2b + (size_t)l * 2 * D;
        gin_dual_kernel<<<gemm_grid, 256, SM_TOTAL>>>(
            i0, i1, wpl, b1p, b2p, hn,
            /*relu_out=*/(l < NUM_LAYER - 1) ? 1 : 0);

        float* tmp = h; h = hn; hn = tmp;
    }

    bounds_kernel<<<1, NGRAPH + 1>>>(batch);
    pool_kernel<<<NGRAPH, D>>>(h, out, out_size);
}